// round 13
// baseline (speedup 1.0000x reference)
#include <cuda_runtime.h>
#include <cuda_fp16.h>
#include <cstdint>

// ---------------------------------------------------------------------------
// VolterraGraphConvLayer on GB300 (sm_103 non-'a': legacy mma.sync only).
//   gemm1: M[p] = A[p] @ X  via fp16 mma.m16n8k16, persistent 148 CTAs,
//          384 tiles of 64x256, dual 8-warp k-split groups (kt mod 2).
//          A operand: DIRECT-from-GMEM register fragments (LDG.64 pairs +
//          1-k16-ahead pipeline + L2 prefetch) -- no smem round trip.
//          B operand: smem ring (2 stages/group) with hperm fp16 layout.
//   gemm2: out = relu([X|S1|S2] @ [W0|W1|W2]^T + bias)  via tf32 mma.
// ---------------------------------------------------------------------------

#define N_NODES 8192
#define DIM     256
#define NPOW    3

__device__ __align__(1024) float  g_M [(size_t)NPOW * N_NODES * DIM];  // 24 MB
__device__ __align__(1024) __half g_Xh[(size_t)DIM * N_NODES];          // 4 MB [feat][node-perm]

// ---------------- PTX helpers ----------------
__device__ __forceinline__ uint32_t smem_u32(const void* p) {
    return (uint32_t)__cvta_generic_to_shared(p);
}
__device__ __forceinline__ void cp_async16(uint32_t dst, const void* src) {
    asm volatile("cp.async.cg.shared.global [%0], [%1], 16;\n" :: "r"(dst), "l"(src));
}
__device__ __forceinline__ void cp_commit() { asm volatile("cp.async.commit_group;\n"); }
template <int N> __device__ __forceinline__ void cp_wait() {
    asm volatile("cp.async.wait_group %0;\n" :: "n"(N));
}
__device__ __forceinline__ void bar_named(int id, int cnt) {
    asm volatile("bar.sync %0, %1;" :: "r"(id), "r"(cnt) : "memory");
}
__device__ __forceinline__ void pf_l2(const void* p) {
    asm volatile("prefetch.global.L2 [%0];" :: "l"(p));
}
__device__ __forceinline__ uint32_t f2tf32(float x) {
    uint32_t r; asm("cvt.rna.tf32.f32 %0, %1;\n" : "=r"(r) : "f"(x)); return r;
}
__device__ __forceinline__ void lds64(uint32_t& x, uint32_t& y, uint32_t a) {
    asm volatile("ld.shared.v2.b32 {%0,%1}, [%2];" : "=r"(x), "=r"(y) : "r"(a));
}
__device__ __forceinline__ void sts128f(uint32_t a, float x, float y, float z, float w) {
    asm volatile("st.shared.v4.f32 [%0], {%1,%2,%3,%4};" :: "r"(a), "f"(x), "f"(y), "f"(z), "f"(w));
}
__device__ __forceinline__ void lds128f(float& x, float& y, float& z, float& w, uint32_t a) {
    asm volatile("ld.shared.v4.f32 {%0,%1,%2,%3}, [%4];" : "=f"(x), "=f"(y), "=f"(z), "=f"(w) : "r"(a));
}
__device__ __forceinline__ void mma_f16(float c[4],
                                        uint32_t a0, uint32_t a1, uint32_t a2, uint32_t a3,
                                        uint32_t b0, uint32_t b1) {
    asm volatile(
        "mma.sync.aligned.m16n8k16.row.col.f32.f16.f16.f32 "
        "{%0,%1,%2,%3}, {%4,%5,%6,%7}, {%8,%9}, {%0,%1,%2,%3};\n"
        : "+f"(c[0]), "+f"(c[1]), "+f"(c[2]), "+f"(c[3])
        : "r"(a0), "r"(a1), "r"(a2), "r"(a3), "r"(b0), "r"(b1));
}
__device__ __forceinline__ void mma_tf32(float c[4],
                                         uint32_t a0, uint32_t a1, uint32_t a2, uint32_t a3,
                                         uint32_t b0, uint32_t b1) {
    asm volatile(
        "mma.sync.aligned.m16n8k8.row.col.f32.tf32.tf32.f32 "
        "{%0,%1,%2,%3}, {%4,%5,%6,%7}, {%8,%9}, {%0,%1,%2,%3};\n"
        : "+f"(c[0]), "+f"(c[1]), "+f"(c[2]), "+f"(c[3])
        : "r"(a0), "r"(a1), "r"(a2), "r"(a3), "r"(b0), "r"(b1));
}
__device__ __forceinline__ uint32_t h2u(__half2 h) {
    return *reinterpret_cast<uint32_t*>(&h);
}
__device__ __forceinline__ float2 ldg2(const float* p) {
    float2 v;
    asm volatile("ld.global.nc.v2.f32 {%0,%1}, [%2];" : "=f"(v.x), "=f"(v.y) : "l"(p));
    return v;
}

// k-within-16 interleave: positions 4t..4t+3 hold original k {2t,2t+1,2t+8,2t+9}
__device__ __forceinline__ int hperm(int k) {
    return ((k & 7) >> 1) * 4 + ((k >> 3) & 1) * 2 + (k & 1);
}

// ---------------------------------------------------------------------------
// Kernel 0: g_Xh[feat][perm(node)] = fp16_rna(X[node][feat])
// ---------------------------------------------------------------------------
__global__ void __launch_bounds__(256)
prep_xh(const float* __restrict__ X) {
    __shared__ float t[32][33];
    const int n0 = blockIdx.x * 32;
    const int f0 = blockIdx.y * 32;
    const int tx = threadIdx.x, ty = threadIdx.y;
#pragma unroll
    for (int j = 0; j < 32; j += 8)
        t[ty + j][tx] = X[(size_t)(n0 + ty + j) * DIM + f0 + tx];
    __syncthreads();
    const int node = n0 + tx;
    const int ndst = (node & ~15) + hperm(node & 15);
#pragma unroll
    for (int j = 0; j < 32; j += 8)
        g_Xh[(size_t)(f0 + ty + j) * N_NODES + ndst] = __float2half_rn(t[tx][ty + j]);
}

// ---------------------------------------------------------------------------
// Kernel 1: persistent fp16 GEMM, k-split dual-group CTA, A-direct fragments.
// Tile 64x256, BK=64. Group g (256 threads) does kts g, g+2, ... (64 each).
// Per group smem: B only, 2 stages x 256x160B = 80 KB.
// ---------------------------------------------------------------------------
#define B_ROWB    160
#define B_STAGEB  (256 * B_ROWB)          // 40960
#define GRP_BYTES (2 * B_STAGEB)          // 81920
#define G1_SMEM   (2 * GRP_BYTES + 1024)  // 164864
#define NTG       64
#define TILES     (NPOW * (N_NODES / 64)) // 384
#define GRID1     148

__global__ void __launch_bounds__(512, 1)
volterra_gemm1(const float* __restrict__ A) {
    extern __shared__ char dsm[];
    const uint32_t base = (smem_u32(dsm) + 1023) & ~1023u;

    const int tid   = threadIdx.x;
    const int grp   = tid >> 8;           // 0 or 1
    const int gtid  = tid & 255;
    const int wid_g = gtid >> 5;          // 0..7 within group
    const int lane  = tid & 31;
    const int g     = lane >> 2;
    const int tq    = lane & 3;
    const int rw0   = (wid_g >> 2) * 32;  // 2 row groups of 32
    const int cw0   = (wid_g & 3) * 64;   // 4 col groups of 64

    const uint32_t gbase = base + (uint32_t)grp * GRP_BYTES;
    const uint32_t bCp   = gbase;
    const uint32_t bFrag = gbase + (uint32_t)(cw0 + g) * B_ROWB + tq * 8;
    const int barId = grp + 1;

    for (int t = blockIdx.x; t < TILES; t += GRID1) {
        const int p    = t >> 7;
        const int row0 = (t & 127) * 64;
        const float* Ap = A + (size_t)p * N_NODES * N_NODES;
        // per-lane A pointers (fragment rows); cols added per k16
        const float* aP = Ap + (size_t)(row0 + rw0 + g) * N_NODES + 2 * tq;
        // per-lane L2 prefetch row bases (2 instrs cover the warp's 32x64 f32)
        const float* pfP0 = Ap + (size_t)(row0 + rw0 + g + 8 * (tq & 1)) * N_NODES + (tq >> 1) * 32;
        const float* pfP1 = pfP0 + 16 * N_NODES;

        float acc[2][8][4];
#pragma unroll
        for (int mt = 0; mt < 2; mt++)
#pragma unroll
            for (int nt = 0; nt < 8; nt++)
#pragma unroll
                for (int i = 0; i < 4; i++) acc[mt][nt][i] = 0.f;

        auto cpB = [&](int j) {            // async B tile into stage j&1
            const uint32_t sb = bCp + (j & 1) * B_STAGEB;
            const int k0 = (2 * j + grp) * 64;
#pragma unroll
            for (int i = 0; i < 8; i++) {
                int idx = gtid + i * 256;
                int n = idx >> 3, c = idx & 7;
                cp_async16(sb + (uint32_t)n * B_ROWB + c * 16,
                           g_Xh + (size_t)n * N_NODES + k0 + c * 8);
            }
            cp_commit();
        };

        float2 pfr[8];                     // next-k16 A f32 pairs (16 regs)
        auto ldA = [&](int col) {          // 8 LDG.64 for one k16 slab
            const float* q = aP + col;
            pfr[0] = ldg2(q);
            pfr[1] = ldg2(q + 8 * N_NODES);
            pfr[2] = ldg2(q + 8);
            pfr[3] = ldg2(q + 8 * N_NODES + 8);
            pfr[4] = ldg2(q + 16 * N_NODES);
            pfr[5] = ldg2(q + 24 * N_NODES);
            pfr[6] = ldg2(q + 16 * N_NODES + 8);
            pfr[7] = ldg2(q + 24 * N_NODES + 8);
        };

        cpB(0);
        ldA(grp * 64);                     // kt0 (this group), k16=0

        for (int j = 0; j < NTG; j++) {
            bar_named(barId, 256);               // group done reading stage (j+1)&1
            if (j + 1 < NTG) { cpB(j + 1); cp_wait<1>(); }
            else             cp_wait<0>();
            bar_named(barId, 256);               // B(j) visible to whole group

            const uint32_t bS = bFrag + (j & 1) * B_STAGEB;
            const int colbase = (2 * j + grp) * 64;
            const int colnextkt = (j + 1 < NTG) ? (2 * (j + 1) + grp) * 64 : 0;

            if (j + 1 < NTG) {                   // L2 prefetch next kt's A slab
                pf_l2(pfP0 + colnextkt);
                pf_l2(pfP1 + colnextkt);
            }

#pragma unroll
            for (int k16 = 0; k16 < 4; k16++) {
                // convert the prefetched f32 pairs -> fp16 fragments
                uint32_t af[8];
#pragma unroll
                for (int i = 0; i < 8; i++)
                    af[i] = h2u(__floats2half2_rn(pfr[i].x, pfr[i].y));
                // issue LDGs for the next k16 slab (wraps to next kt at k16==3)
                const int ncol = (k16 < 3) ? (colbase + (k16 + 1) * 16) : colnextkt;
                ldA(ncol);
                // batched B fragment loads for this k16
                uint32_t bb[16];
                const uint32_t off = k16 * 32;
#pragma unroll
                for (int nt = 0; nt < 8; nt++)
                    lds64(bb[2 * nt], bb[2 * nt + 1], bS + nt * 8 * B_ROWB + off);
#pragma unroll
                for (int nt = 0; nt < 8; nt++) {
                    mma_f16(acc[0][nt], af[0], af[1], af[2], af[3], bb[2 * nt], bb[2 * nt + 1]);
                    mma_f16(acc[1][nt], af[4], af[5], af[6], af[7], bb[2 * nt], bb[2 * nt + 1]);
                }
            }
        }

        // ---- cross-group accumulator reduction + store ----
        const uint32_t red = base + GRP_BYTES;   // group1's B region (80KB >= 64KB)
        __syncthreads();
        if (grp == 1) {
            const uint32_t w = red + (uint32_t)wid_g * 8192 + lane * 16;
#pragma unroll
            for (int mt = 0; mt < 2; mt++)
#pragma unroll
                for (int nt = 0; nt < 8; nt++)
                    sts128f(w + (mt * 8 + nt) * 512,
                            acc[mt][nt][0], acc[mt][nt][1], acc[mt][nt][2], acc[mt][nt][3]);
        }
        __syncthreads();
        if (grp == 0) {
            const uint32_t r = red + (uint32_t)wid_g * 8192 + lane * 16;
            float* Mo = g_M + (size_t)p * N_NODES * DIM;
#pragma unroll
            for (int mt = 0; mt < 2; mt++) {
                const int rr = row0 + rw0 + mt * 16 + g;
#pragma unroll
                for (int nt = 0; nt < 8; nt++) {
                    float x, y, z, w2;
                    lds128f(x, y, z, w2, r + (mt * 8 + nt) * 512);
                    const int c = cw0 + nt * 8 + 2 * tq;
                    *(float2*)&Mo[(size_t)rr * DIM + c] =
                        make_float2(acc[mt][nt][0] + x, acc[mt][nt][1] + y);
                    *(float2*)&Mo[(size_t)(rr + 8) * DIM + c] =
                        make_float2(acc[mt][nt][2] + z, acc[mt][nt][3] + w2);
                }
            }
        }
        __syncthreads();   // red region reused as B stages next tile
    }
}

// ---------------------------------------------------------------------------
// Kernel 2:  out = relu( [X | S1 | S2] @ [W0 | W1 | W2]^T + bias )   (tf32)
// ---------------------------------------------------------------------------
#define TS_STRIDE 36
__global__ void __launch_bounds__(256)
volterra_gemm2(const float* __restrict__ X, const float* __restrict__ W,
               const float* __restrict__ bvec, float* __restrict__ out) {
    __shared__ float Ts[64][TS_STRIDE];
    __shared__ float Ws[128][TS_STRIDE];

    const int row0 = blockIdx.x * 64;
    const int col0 = blockIdx.y * 128;
    const int tid  = threadIdx.x;
    const int wid  = tid >> 5;
    const int lane = tid & 31;
    const int warpRow = (wid >> 2) * 32;
    const int warpCol = (wid & 3) * 32;

    float acc[2][4][4];
#pragma unroll
    for (int mt = 0; mt < 2; mt++)
#pragma unroll
        for (int nt = 0; nt < 4; nt++)
#pragma unroll
            for (int i = 0; i < 4; i++) acc[mt][nt][i] = 0.f;

    const size_t MSZ = (size_t)N_NODES * DIM;

    for (int kc = 0; kc < 24; kc++) {
        const int r  = kc >> 3;
        const int k0 = (kc & 7) * 32;

#pragma unroll
        for (int i = 0; i < 2; i++) {
            int idx = tid + i * 256;
            int rr = idx >> 3, c4 = idx & 7;
            size_t gidx = (size_t)(row0 + rr) * DIM + k0 + c4 * 4;
            float4 v;
            if (r == 0) {
                v = *(const float4*)&X[gidx];
            } else {
                float4 m0 = *(const float4*)&g_M[gidx];
                float4 m1 = *(const float4*)&g_M[MSZ + gidx];
                float4 m2 = *(const float4*)&g_M[2 * MSZ + gidx];
                if (r == 1) {
                    v.x = m0.x + m1.x + m2.x;  v.y = m0.y + m1.y + m2.y;
                    v.z = m0.z + m1.z + m2.z;  v.w = m0.w + m1.w + m2.w;
                } else {
                    float s, q;
                    s = m0.x + m1.x + m2.x; q = m0.x*m0.x + m1.x*m1.x + m2.x*m2.x; v.x = 0.5f*(s*s + q);
                    s = m0.y + m1.y + m2.y; q = m0.y*m0.y + m1.y*m1.y + m2.y*m2.y; v.y = 0.5f*(s*s + q);
                    s = m0.z + m1.z + m2.z; q = m0.z*m0.z + m1.z*m1.z + m2.z*m2.z; v.z = 0.5f*(s*s + q);
                    s = m0.w + m1.w + m2.w; q = m0.w*m0.w + m1.w*m1.w + m2.w*m2.w; v.w = 0.5f*(s*s + q);
                }
            }
            *(float4*)&Ts[rr][c4 * 4] = v;
        }
        const float* Wr = W + (size_t)r * DIM * DIM;
#pragma unroll
        for (int i = 0; i < 4; i++) {
            int idx = tid + i * 256;
            int d = idx >> 3, c4 = idx & 7;
            *(float4*)&Ws[d][c4 * 4] = *(const float4*)&Wr[(size_t)(col0 + d) * DIM + k0 + c4 * 4];
        }
        __syncthreads();

#pragma unroll
        for (int k8 = 0; k8 < 4; k8++) {
            const int kb = k8 * 8;
            uint32_t af[2][4];
#pragma unroll
            for (int mt = 0; mt < 2; mt++) {
                int rr = warpRow + mt * 16 + (lane >> 2);
                int c = kb + (lane & 3);
                af[mt][0] = f2tf32(Ts[rr][c]);
                af[mt][1] = f2tf32(Ts[rr + 8][c]);
                af[mt][2] = f2tf32(Ts[rr][c + 4]);
                af[mt][3] = f2tf32(Ts[rr + 8][c + 4]);
            }
#pragma unroll
            for (int nt = 0; nt < 4; nt++) {
                int d = warpCol + nt * 8 + (lane >> 2);
                int k = kb + (lane & 3);
                uint32_t b0 = f2tf32(Ws[d][k]);
                uint32_t b1 = f2tf32(Ws[d][k + 4]);
                mma_tf32(acc[0][nt], af[0][0], af[0][1], af[0][2], af[0][3], b0, b1);
                mma_tf32(acc[1][nt], af[1][0], af[1][1], af[1][2], af[1][3], b0, b1);
            }
        }
        __syncthreads();
    }

#pragma unroll
    for (int nt = 0; nt < 4; nt++) {
        int c  = col0 + warpCol + nt * 8 + 2 * (lane & 3);
        float bias0 = bvec[c]     + 3.f * bvec[DIM + c]     + 6.f * bvec[2 * DIM + c];
        float bias1 = bvec[c + 1] + 3.f * bvec[DIM + c + 1] + 6.f * bvec[2 * DIM + c + 1];
#pragma unroll
        for (int mt = 0; mt < 2; mt++) {
            int rr = row0 + warpRow + mt * 16 + (lane >> 2);
            float2 v0 = make_float2(fmaxf(acc[mt][nt][0] + bias0, 0.f),
                                    fmaxf(acc[mt][nt][1] + bias1, 0.f));
            float2 v1 = make_float2(fmaxf(acc[mt][nt][2] + bias0, 0.f),
                                    fmaxf(acc[mt][nt][3] + bias1, 0.f));
            *(float2*)&out[(size_t)rr * DIM + c]       = v0;
            *(float2*)&out[(size_t)(rr + 8) * DIM + c] = v1;
        }
    }
}

// ---------------------------------------------------------------------------
extern "C" void kernel_launch(void* const* d_in, const int* in_sizes, int n_in,
                              void* d_out, int out_size) {
    const float *X = nullptr, *A = nullptr, *W = nullptr, *b = nullptr;
    for (int i = 0; i < n_in; i++) {
        long long s = in_sizes[i];
        if      (s == (long long)N_NODES * DIM)            X = (const float*)d_in[i];
        else if (s == (long long)NPOW * N_NODES * N_NODES) A = (const float*)d_in[i];
        else if (s == (long long)NPOW * DIM * DIM)         W = (const float*)d_in[i];
        else if (s == (long long)NPOW * DIM)               b = (const float*)d_in[i];
    }

    cudaFuncSetAttribute(volterra_gemm1,
                         cudaFuncAttributeMaxDynamicSharedMemorySize, G1_SMEM);

    prep_xh<<<dim3(N_NODES / 32, DIM / 32), dim3(32, 8)>>>(X);
    volterra_gemm1<<<GRID1, 512, G1_SMEM>>>(A);
    volterra_gemm2<<<dim3(N_NODES / 64, 2), 256>>>(X, W, b, (float*)d_out);
}

// round 14
// speedup vs baseline: 1.3368x; 1.3368x over previous
#include <cuda_runtime.h>
#include <cuda_fp16.h>
#include <cstdint>

// ---------------------------------------------------------------------------
// VolterraGraphConvLayer on GB300 (sm_103 non-'a': legacy mma.sync only).
//   gemm1: M[p] = A[p] @ X  via fp16 mma.m16n8k16, persistent 148 CTAs,
//          384 tiles of 64x256, dual 8-warp k-split groups (kt mod 2).
//          Both operands hperm'd in smem so every fragment is one LDS.64;
//          per-k16: 12 batched lds64 then 16 mma (load->use distance).
//   gemm2: out = relu([X|S1|S2] @ [W0|W1|W2]^T + bias)  via tf32 mma.
// ---------------------------------------------------------------------------

#define N_NODES 8192
#define DIM     256
#define NPOW    3

__device__ __align__(1024) float  g_M [(size_t)NPOW * N_NODES * DIM];  // 24 MB
__device__ __align__(1024) __half g_Xh[(size_t)DIM * N_NODES];          // 4 MB [feat][node-perm]

// ---------------- PTX helpers ----------------
__device__ __forceinline__ uint32_t smem_u32(const void* p) {
    return (uint32_t)__cvta_generic_to_shared(p);
}
__device__ __forceinline__ void cp_async16(uint32_t dst, const void* src) {
    asm volatile("cp.async.cg.shared.global [%0], [%1], 16;\n" :: "r"(dst), "l"(src));
}
__device__ __forceinline__ void cp_commit() { asm volatile("cp.async.commit_group;\n"); }
template <int N> __device__ __forceinline__ void cp_wait() {
    asm volatile("cp.async.wait_group %0;\n" :: "n"(N));
}
__device__ __forceinline__ void bar_named(int id, int cnt) {
    asm volatile("bar.sync %0, %1;" :: "r"(id), "r"(cnt) : "memory");
}
__device__ __forceinline__ uint32_t f2tf32(float x) {
    uint32_t r; asm("cvt.rna.tf32.f32 %0, %1;\n" : "=r"(r) : "f"(x)); return r;
}
__device__ __forceinline__ void lds64(uint32_t& x, uint32_t& y, uint32_t a) {
    asm volatile("ld.shared.v2.b32 {%0,%1}, [%2];" : "=r"(x), "=r"(y) : "r"(a));
}
__device__ __forceinline__ void sts64(uint32_t a, uint32_t x, uint32_t y) {
    asm volatile("st.shared.v2.b32 [%0], {%1,%2};" :: "r"(a), "r"(x), "r"(y));
}
__device__ __forceinline__ void sts128f(uint32_t a, float x, float y, float z, float w) {
    asm volatile("st.shared.v4.f32 [%0], {%1,%2,%3,%4};" :: "r"(a), "f"(x), "f"(y), "f"(z), "f"(w));
}
__device__ __forceinline__ void lds128f(float& x, float& y, float& z, float& w, uint32_t a) {
    asm volatile("ld.shared.v4.f32 {%0,%1,%2,%3}, [%4];" : "=f"(x), "=f"(y), "=f"(z), "=f"(w) : "r"(a));
}
__device__ __forceinline__ void mma_f16(float c[4],
                                        uint32_t a0, uint32_t a1, uint32_t a2, uint32_t a3,
                                        uint32_t b0, uint32_t b1) {
    asm volatile(
        "mma.sync.aligned.m16n8k16.row.col.f32.f16.f16.f32 "
        "{%0,%1,%2,%3}, {%4,%5,%6,%7}, {%8,%9}, {%0,%1,%2,%3};\n"
        : "+f"(c[0]), "+f"(c[1]), "+f"(c[2]), "+f"(c[3])
        : "r"(a0), "r"(a1), "r"(a2), "r"(a3), "r"(b0), "r"(b1));
}
__device__ __forceinline__ void mma_tf32(float c[4],
                                         uint32_t a0, uint32_t a1, uint32_t a2, uint32_t a3,
                                         uint32_t b0, uint32_t b1) {
    asm volatile(
        "mma.sync.aligned.m16n8k8.row.col.f32.tf32.tf32.f32 "
        "{%0,%1,%2,%3}, {%4,%5,%6,%7}, {%8,%9}, {%0,%1,%2,%3};\n"
        : "+f"(c[0]), "+f"(c[1]), "+f"(c[2]), "+f"(c[3])
        : "r"(a0), "r"(a1), "r"(a2), "r"(a3), "r"(b0), "r"(b1));
}
__device__ __forceinline__ uint32_t h2u(__half2 h) {
    return *reinterpret_cast<uint32_t*>(&h);
}
__device__ __forceinline__ float2 ldg2(const float* p) {
    float2 v;
    asm volatile("ld.global.nc.v2.f32 {%0,%1}, [%2];" : "=f"(v.x), "=f"(v.y) : "l"(p));
    return v;
}

// k-within-16 interleave: positions 4t..4t+3 hold original k {2t,2t+1,2t+8,2t+9}
__device__ __forceinline__ int hperm(int k) {
    return ((k & 7) >> 1) * 4 + ((k >> 3) & 1) * 2 + (k & 1);
}

// ---------------------------------------------------------------------------
// Kernel 0: g_Xh[feat][perm(node)] = fp16_rna(X[node][feat])
// ---------------------------------------------------------------------------
__global__ void __launch_bounds__(256)
prep_xh(const float* __restrict__ X) {
    __shared__ float t[32][33];
    const int n0 = blockIdx.x * 32;
    const int f0 = blockIdx.y * 32;
    const int tx = threadIdx.x, ty = threadIdx.y;
#pragma unroll
    for (int j = 0; j < 32; j += 8)
        t[ty + j][tx] = X[(size_t)(n0 + ty + j) * DIM + f0 + tx];
    __syncthreads();
    const int node = n0 + tx;
    const int ndst = (node & ~15) + hperm(node & 15);
#pragma unroll
    for (int j = 0; j < 32; j += 8)
        g_Xh[(size_t)(f0 + ty + j) * N_NODES + ndst] = __float2half_rn(t[tx][ty + j]);
}

// ---------------------------------------------------------------------------
// Kernel 1: persistent fp16 GEMM, k-split dual-group CTA.
// Tile 64x256, BK=64. Group g (256 threads) does kts g, g+2, ... (64 each).
// Per group smem: A 2 stages x 64x160B (hperm fp16) + B 2 stages x 256x160B.
// ---------------------------------------------------------------------------
#define A_ROWB    160
#define B_ROWB    160
#define A_STAGEB  (64 * A_ROWB)                   // 10240
#define B_STAGEB  (256 * B_ROWB)                  // 40960
#define GRP_BYTES (2 * A_STAGEB + 2 * B_STAGEB)   // 102400
#define G1_SMEM   (2 * GRP_BYTES + 1024)          // 205824
#define NTG       64
#define TILES     (NPOW * (N_NODES / 64))         // 384
#define GRID1     148

__global__ void __launch_bounds__(512, 1)
volterra_gemm1(const float* __restrict__ A) {
    extern __shared__ char dsm[];
    const uint32_t base = (smem_u32(dsm) + 1023) & ~1023u;

    const int tid   = threadIdx.x;
    const int grp   = tid >> 8;           // 0 or 1
    const int gtid  = tid & 255;
    const int wid_g = gtid >> 5;          // 0..7 within group
    const int lane  = tid & 31;
    const int g     = lane >> 2;
    const int tq    = lane & 3;
    const int rw0   = (wid_g >> 2) * 32;  // 2 row groups of 32
    const int cw0   = (wid_g & 3) * 64;   // 4 col groups of 64

    // A-load mapping: thread -> (i_, q_, r0_); rows r0_+16m, k = 16q_+{2i_,2i_+1,2i_+8,2i_+9}
    const int i_  = gtid & 3;
    const int q_  = (gtid >> 2) & 3;
    const int r0_ = gtid >> 4;            // 0..15

    const uint32_t gbase = base + (uint32_t)grp * GRP_BYTES;
    const uint32_t aSts  = gbase;
    const uint32_t bCp   = gbase + 2 * A_STAGEB;
    const uint32_t aFrag = gbase + (uint32_t)(rw0 + g) * A_ROWB + tq * 8;
    const uint32_t bFrag = bCp + (uint32_t)(cw0 + g) * B_ROWB + tq * 8;
    const int barId = grp + 1;

    for (int t = blockIdx.x; t < TILES; t += GRID1) {
        const int p    = t >> 7;
        const int row0 = (t & 127) * 64;
        const float* Ap = A + (size_t)p * N_NODES * N_NODES;

        float acc[2][8][4];
#pragma unroll
        for (int mt = 0; mt < 2; mt++)
#pragma unroll
            for (int nt = 0; nt < 8; nt++)
#pragma unroll
                for (int i = 0; i < 4; i++) acc[mt][nt][i] = 0.f;

        float2 buf[8];                     // A staging: 4 slots x 2 float2

        auto ldgA = [&](int j) {           // load A slab for local iter j
            const int k0 = (2 * j + grp) * 64 + 16 * q_ + 2 * i_;
#pragma unroll
            for (int m = 0; m < 4; m++) {
                const float* q = Ap + (size_t)(row0 + r0_ + 16 * m) * N_NODES + k0;
                buf[2 * m]     = ldg2(q);
                buf[2 * m + 1] = ldg2(q + 8);
            }
        };
        auto stsA = [&](int j) {           // convert + store hperm'd into stage j&1
            const uint32_t sa = aSts + (j & 1) * A_STAGEB;
#pragma unroll
            for (int m = 0; m < 4; m++) {
                uint32_t u0 = h2u(__floats2half2_rn(buf[2 * m].x, buf[2 * m].y));
                uint32_t u1 = h2u(__floats2half2_rn(buf[2 * m + 1].x, buf[2 * m + 1].y));
                sts64(sa + (uint32_t)(r0_ + 16 * m) * A_ROWB + q_ * 32 + i_ * 8, u0, u1);
            }
        };
        auto cpB = [&](int j) {            // async B tile into stage j&1
            const uint32_t sb = bCp + (j & 1) * B_STAGEB;
            const int k0 = (2 * j + grp) * 64;
#pragma unroll
            for (int i = 0; i < 8; i++) {
                int idx = gtid + i * 256;
                int n = idx >> 3, c = idx & 7;
                cp_async16(sb + (uint32_t)n * B_ROWB + c * 16,
                           g_Xh + (size_t)n * N_NODES + k0 + c * 8);
            }
            cp_commit();
        };

        // prologue: A(0) ldg+sts, A(1) ldg into regs, B(0) in flight
        ldgA(0); cpB(0); stsA(0); ldgA(1);

        for (int j = 0; j < NTG; j++) {
            bar_named(barId, 256);               // group done reading stage (j+1)&1
            if (j + 1 < NTG) { cpB(j + 1); stsA(j + 1); }
            if (j + 2 < NTG) ldgA(j + 2);
            if (j + 1 < NTG) cp_wait<1>(); else cp_wait<0>();
            bar_named(barId, 256);               // B(j)/A(j) visible to whole group

            const uint32_t aS = aFrag + (j & 1) * A_STAGEB;
            const uint32_t bS = bFrag + (j & 1) * B_STAGEB;
#pragma unroll
            for (int k16 = 0; k16 < 4; k16++) {
                const uint32_t off = k16 * 32;
                // A fragments: 4 lds64 (hperm layout -> (low,high) pairs)
                uint32_t a0a, a2a, a1a, a3a, a0b, a2b, a1b, a3b;
                lds64(a0a, a2a, aS + off);
                lds64(a1a, a3a, aS + off + 8 * A_ROWB);
                lds64(a0b, a2b, aS + off + 16 * A_ROWB);
                lds64(a1b, a3b, aS + off + 24 * A_ROWB);
                // B fragments: 8 lds64, batched
                uint32_t bb[16];
#pragma unroll
                for (int nt = 0; nt < 8; nt++)
                    lds64(bb[2 * nt], bb[2 * nt + 1], bS + nt * 8 * B_ROWB + off);
                // 16 mma
#pragma unroll
                for (int nt = 0; nt < 8; nt++) {
                    mma_f16(acc[0][nt], a0a, a1a, a2a, a3a, bb[2 * nt], bb[2 * nt + 1]);
                    mma_f16(acc[1][nt], a0b, a1b, a2b, a3b, bb[2 * nt], bb[2 * nt + 1]);
                }
            }
        }

        // ---- cross-group accumulator reduction + store ----
        const uint32_t red = base + GRP_BYTES + 2 * A_STAGEB;  // group1's B region (80KB >= 64KB)
        __syncthreads();
        if (grp == 1) {
            const uint32_t w = red + (uint32_t)wid_g * 8192 + lane * 16;
#pragma unroll
            for (int mt = 0; mt < 2; mt++)
#pragma unroll
                for (int nt = 0; nt < 8; nt++)
                    sts128f(w + (mt * 8 + nt) * 512,
                            acc[mt][nt][0], acc[mt][nt][1], acc[mt][nt][2], acc[mt][nt][3]);
        }
        __syncthreads();
        if (grp == 0) {
            const uint32_t r = red + (uint32_t)wid_g * 8192 + lane * 16;
            float* Mo = g_M + (size_t)p * N_NODES * DIM;
#pragma unroll
            for (int mt = 0; mt < 2; mt++) {
                const int rr = row0 + rw0 + mt * 16 + g;
#pragma unroll
                for (int nt = 0; nt < 8; nt++) {
                    float x, y, z, w2;
                    lds128f(x, y, z, w2, r + (mt * 8 + nt) * 512);
                    const int c = cw0 + nt * 8 + 2 * tq;
                    *(float2*)&Mo[(size_t)rr * DIM + c] =
                        make_float2(acc[mt][nt][0] + x, acc[mt][nt][1] + y);
                    *(float2*)&Mo[(size_t)(rr + 8) * DIM + c] =
                        make_float2(acc[mt][nt][2] + z, acc[mt][nt][3] + w2);
                }
            }
        }
        __syncthreads();   // red region reused as B stages next tile
    }
}

// ---------------------------------------------------------------------------
// Kernel 2:  out = relu( [X | S1 | S2] @ [W0 | W1 | W2]^T + bias )   (tf32)
// ---------------------------------------------------------------------------
#define TS_STRIDE 36
__global__ void __launch_bounds__(256)
volterra_gemm2(const float* __restrict__ X, const float* __restrict__ W,
               const float* __restrict__ bvec, float* __restrict__ out) {
    __shared__ float Ts[64][TS_STRIDE];
    __shared__ float Ws[128][TS_STRIDE];

    const int row0 = blockIdx.x * 64;
    const int col0 = blockIdx.y * 128;
    const int tid  = threadIdx.x;
    const int wid  = tid >> 5;
    const int lane = tid & 31;
    const int warpRow = (wid >> 2) * 32;
    const int warpCol = (wid & 3) * 32;

    float acc[2][4][4];
#pragma unroll
    for (int mt = 0; mt < 2; mt++)
#pragma unroll
        for (int nt = 0; nt < 4; nt++)
#pragma unroll
            for (int i = 0; i < 4; i++) acc[mt][nt][i] = 0.f;

    const size_t MSZ = (size_t)N_NODES * DIM;

    for (int kc = 0; kc < 24; kc++) {
        const int r  = kc >> 3;
        const int k0 = (kc & 7) * 32;

#pragma unroll
        for (int i = 0; i < 2; i++) {
            int idx = tid + i * 256;
            int rr = idx >> 3, c4 = idx & 7;
            size_t gidx = (size_t)(row0 + rr) * DIM + k0 + c4 * 4;
            float4 v;
            if (r == 0) {
                v = *(const float4*)&X[gidx];
            } else {
                float4 m0 = *(const float4*)&g_M[gidx];
                float4 m1 = *(const float4*)&g_M[MSZ + gidx];
                float4 m2 = *(const float4*)&g_M[2 * MSZ + gidx];
                if (r == 1) {
                    v.x = m0.x + m1.x + m2.x;  v.y = m0.y + m1.y + m2.y;
                    v.z = m0.z + m1.z + m2.z;  v.w = m0.w + m1.w + m2.w;
                } else {
                    float s, q;
                    s = m0.x + m1.x + m2.x; q = m0.x*m0.x + m1.x*m1.x + m2.x*m2.x; v.x = 0.5f*(s*s + q);
                    s = m0.y + m1.y + m2.y; q = m0.y*m0.y + m1.y*m1.y + m2.y*m2.y; v.y = 0.5f*(s*s + q);
                    s = m0.z + m1.z + m2.z; q = m0.z*m0.z + m1.z*m1.z + m2.z*m2.z; v.z = 0.5f*(s*s + q);
                    s = m0.w + m1.w + m2.w; q = m0.w*m0.w + m1.w*m1.w + m2.w*m2.w; v.w = 0.5f*(s*s + q);
                }
            }
            *(float4*)&Ts[rr][c4 * 4] = v;
        }
        const float* Wr = W + (size_t)r * DIM * DIM;
#pragma unroll
        for (int i = 0; i < 4; i++) {
            int idx = tid + i * 256;
            int d = idx >> 3, c4 = idx & 7;
            *(float4*)&Ws[d][c4 * 4] = *(const float4*)&Wr[(size_t)(col0 + d) * DIM + k0 + c4 * 4];
        }
        __syncthreads();

#pragma unroll
        for (int k8 = 0; k8 < 4; k8++) {
            const int kb = k8 * 8;
            uint32_t af[2][4];
#pragma unroll
            for (int mt = 0; mt < 2; mt++) {
                int rr = warpRow + mt * 16 + (lane >> 2);
                int c = kb + (lane & 3);
                af[mt][0] = f2tf32(Ts[rr][c]);
                af[mt][1] = f2tf32(Ts[rr + 8][c]);
                af[mt][2] = f2tf32(Ts[rr][c + 4]);
                af[mt][3] = f2tf32(Ts[rr + 8][c + 4]);
            }
#pragma unroll
            for (int nt = 0; nt < 4; nt++) {
                int d = warpCol + nt * 8 + (lane >> 2);
                int k = kb + (lane & 3);
                uint32_t b0 = f2tf32(Ws[d][k]);
                uint32_t b1 = f2tf32(Ws[d][k + 4]);
                mma_tf32(acc[0][nt], af[0][0], af[0][1], af[0][2], af[0][3], b0, b1);
                mma_tf32(acc[1][nt], af[1][0], af[1][1], af[1][2], af[1][3], b0, b1);
            }
        }
        __syncthreads();
    }

#pragma unroll
    for (int nt = 0; nt < 4; nt++) {
        int c  = col0 + warpCol + nt * 8 + 2 * (lane & 3);
        float bias0 = bvec[c]     + 3.f * bvec[DIM + c]     + 6.f * bvec[2 * DIM + c];
        float bias1 = bvec[c + 1] + 3.f * bvec[DIM + c + 1] + 6.f * bvec[2 * DIM + c + 1];
#pragma unroll
        for (int mt = 0; mt < 2; mt++) {
            int rr = row0 + warpRow + mt * 16 + (lane >> 2);
            float2 v0 = make_float2(fmaxf(acc[mt][nt][0] + bias0, 0.f),
                                    fmaxf(acc[mt][nt][1] + bias1, 0.f));
            float2 v1 = make_float2(fmaxf(acc[mt][nt][2] + bias0, 0.f),
                                    fmaxf(acc[mt][nt][3] + bias1, 0.f));
            *(float2*)&out[(size_t)rr * DIM + c]       = v0;
            *(float2*)&out[(size_t)(rr + 8) * DIM + c] = v1;
        }
    }
}

// ---------------------------------------------------------------------------
extern "C" void kernel_launch(void* const* d_in, const int* in_sizes, int n_in,
                              void* d_out, int out_size) {
    const float *X = nullptr, *A = nullptr, *W = nullptr, *b = nullptr;
    for (int i = 0; i < n_in; i++) {
        long long s = in_sizes[i];
        if      (s == (long long)N_NODES * DIM)            X = (const float*)d_in[i];
        else if (s == (long long)NPOW * N_NODES * N_NODES) A = (const float*)d_in[i];
        else if (s == (long long)NPOW * DIM * DIM)         W = (const float*)d_in[i];
        else if (s == (long long)NPOW * DIM)               b = (const float*)d_in[i];
    }

    cudaFuncSetAttribute(volterra_gemm1,
                         cudaFuncAttributeMaxDynamicSharedMemorySize, G1_SMEM);

    prep_xh<<<dim3(N_NODES / 32, DIM / 32), dim3(32, 8)>>>(X);
    volterra_gemm1<<<GRID1, 512, G1_SMEM>>>(A);
    volterra_gemm2<<<dim3(N_NODES / 64, 2), 256>>>(X, W, b, (float*)d_out);
}

// round 15
// speedup vs baseline: 1.4336x; 1.0724x over previous
#include <cuda_runtime.h>
#include <cuda_fp16.h>
#include <cstdint>

// ---------------------------------------------------------------------------
// VolterraGraphConvLayer on GB300 (sm_103 non-'a': legacy mma.sync only).
//   gemm1: M[p] = A[p] @ X  via fp16 mma.m16n8k16, persistent 148 CTAs,
//          384 tiles of 64x256, dual 8-warp k-split groups (kt mod 2).
//          R11 base (best: 470us) + (1) stsA/ldgA deferred past compute to
//          shrink the bar->bar front section, (2) 1-deep bb software pipeline.
//   gemm2: out = relu([X|S1|S2] @ [W0|W1|W2]^T + bias)  via tf32 mma.
// ---------------------------------------------------------------------------

#define N_NODES 8192
#define DIM     256
#define NPOW    3

__device__ __align__(1024) float  g_M [(size_t)NPOW * N_NODES * DIM];  // 24 MB
__device__ __align__(1024) __half g_Xh[(size_t)DIM * N_NODES];          // 4 MB [feat][node-perm]

// ---------------- PTX helpers ----------------
__device__ __forceinline__ uint32_t smem_u32(const void* p) {
    return (uint32_t)__cvta_generic_to_shared(p);
}
__device__ __forceinline__ void cp_async16(uint32_t dst, const void* src) {
    asm volatile("cp.async.cg.shared.global [%0], [%1], 16;\n" :: "r"(dst), "l"(src));
}
__device__ __forceinline__ void cp_commit() { asm volatile("cp.async.commit_group;\n"); }
template <int N> __device__ __forceinline__ void cp_wait() {
    asm volatile("cp.async.wait_group %0;\n" :: "n"(N));
}
__device__ __forceinline__ void bar_named(int id, int cnt) {
    asm volatile("bar.sync %0, %1;" :: "r"(id), "r"(cnt) : "memory");
}
__device__ __forceinline__ uint32_t f2tf32(float x) {
    uint32_t r; asm("cvt.rna.tf32.f32 %0, %1;\n" : "=r"(r) : "f"(x)); return r;
}
__device__ __forceinline__ uint32_t lds32(uint32_t a) {
    uint32_t r; asm volatile("ld.shared.b32 %0, [%1];" : "=r"(r) : "r"(a)); return r;
}
__device__ __forceinline__ void lds64(uint32_t& x, uint32_t& y, uint32_t a) {
    asm volatile("ld.shared.v2.b32 {%0,%1}, [%2];" : "=r"(x), "=r"(y) : "r"(a));
}
__device__ __forceinline__ void sts64(uint32_t a, uint32_t x, uint32_t y) {
    asm volatile("st.shared.v2.b32 [%0], {%1,%2};" :: "r"(a), "r"(x), "r"(y));
}
__device__ __forceinline__ void sts128f(uint32_t a, float x, float y, float z, float w) {
    asm volatile("st.shared.v4.f32 [%0], {%1,%2,%3,%4};" :: "r"(a), "f"(x), "f"(y), "f"(z), "f"(w));
}
__device__ __forceinline__ void lds128f(float& x, float& y, float& z, float& w, uint32_t a) {
    asm volatile("ld.shared.v4.f32 {%0,%1,%2,%3}, [%4];" : "=f"(x), "=f"(y), "=f"(z), "=f"(w) : "r"(a));
}
__device__ __forceinline__ void mma_f16(float c[4],
                                        uint32_t a0, uint32_t a1, uint32_t a2, uint32_t a3,
                                        uint32_t b0, uint32_t b1) {
    asm volatile(
        "mma.sync.aligned.m16n8k16.row.col.f32.f16.f16.f32 "
        "{%0,%1,%2,%3}, {%4,%5,%6,%7}, {%8,%9}, {%0,%1,%2,%3};\n"
        : "+f"(c[0]), "+f"(c[1]), "+f"(c[2]), "+f"(c[3])
        : "r"(a0), "r"(a1), "r"(a2), "r"(a3), "r"(b0), "r"(b1));
}
__device__ __forceinline__ void mma_tf32(float c[4],
                                         uint32_t a0, uint32_t a1, uint32_t a2, uint32_t a3,
                                         uint32_t b0, uint32_t b1) {
    asm volatile(
        "mma.sync.aligned.m16n8k8.row.col.f32.tf32.tf32.f32 "
        "{%0,%1,%2,%3}, {%4,%5,%6,%7}, {%8,%9}, {%0,%1,%2,%3};\n"
        : "+f"(c[0]), "+f"(c[1]), "+f"(c[2]), "+f"(c[3])
        : "r"(a0), "r"(a1), "r"(a2), "r"(a3), "r"(b0), "r"(b1));
}
__device__ __forceinline__ uint32_t h2u(__half2 h) {
    return *reinterpret_cast<uint32_t*>(&h);
}

// k-within-16 interleave: positions 4t..4t+3 hold original k {2t,2t+1,2t+8,2t+9}
__device__ __forceinline__ int hperm(int k) {
    return ((k & 7) >> 1) * 4 + ((k >> 3) & 1) * 2 + (k & 1);
}

// ---------------------------------------------------------------------------
// Kernel 0: g_Xh[feat][perm(node)] = fp16_rna(X[node][feat])
// ---------------------------------------------------------------------------
__global__ void __launch_bounds__(256)
prep_xh(const float* __restrict__ X) {
    __shared__ float t[32][33];
    const int n0 = blockIdx.x * 32;
    const int f0 = blockIdx.y * 32;
    const int tx = threadIdx.x, ty = threadIdx.y;
#pragma unroll
    for (int j = 0; j < 32; j += 8)
        t[ty + j][tx] = X[(size_t)(n0 + ty + j) * DIM + f0 + tx];
    __syncthreads();
    const int node = n0 + tx;
    const int ndst = (node & ~15) + hperm(node & 15);
#pragma unroll
    for (int j = 0; j < 32; j += 8)
        g_Xh[(size_t)(f0 + ty + j) * N_NODES + ndst] = __float2half_rn(t[tx][ty + j]);
}

// ---------------------------------------------------------------------------
// Kernel 1: persistent fp16 GEMM, k-split dual-group CTA (R11 base).
// Tile 64x256, BK=64. Group g (256 threads) does kts g, g+2, ... (64 each).
// Per group: A 2 stages x 64x144B, B 2 stages x 256x160B  -> 100352 B.
// ---------------------------------------------------------------------------
#define A_ROWB    144
#define B_ROWB    160
#define A_STAGEB  (64 * A_ROWB)                   // 9216
#define B_STAGEB  (256 * B_ROWB)                  // 40960
#define GRP_BYTES (2 * A_STAGEB + 2 * B_STAGEB)   // 100352
#define G1_SMEM   (2 * GRP_BYTES + 1024)          // 201728
#define NTG       64
#define TILES     (NPOW * (N_NODES / 64))         // 384
#define GRID1     148

__global__ void __launch_bounds__(512, 1)
volterra_gemm1(const float* __restrict__ A) {
    extern __shared__ char dsm[];
    const uint32_t base = (smem_u32(dsm) + 1023) & ~1023u;

    const int tid   = threadIdx.x;
    const int grp   = tid >> 8;           // 0 or 1
    const int gtid  = tid & 255;
    const int wid_g = gtid >> 5;          // 0..7 within group
    const int lane  = tid & 31;
    const int g     = lane >> 2;
    const int tq    = lane & 3;
    const int rw0   = (wid_g >> 2) * 32;  // 2 row groups of 32
    const int cw0   = (wid_g & 3) * 64;   // 4 col groups of 64

    const int lr0 = gtid >> 4;            // A-load rows: lr0 + 16*i
    const int lk  = (gtid & 15) * 4;

    const uint32_t gbase = base + (uint32_t)grp * GRP_BYTES;
    const uint32_t aSts  = gbase;
    const uint32_t bCp   = gbase + 2 * A_STAGEB;
    const uint32_t aFrag = gbase + (uint32_t)(rw0 + g) * A_ROWB + tq * 4;
    const uint32_t bFrag = bCp + (uint32_t)(cw0 + g) * B_ROWB + tq * 8;
    const int barId = grp + 1;

    for (int t = blockIdx.x; t < TILES; t += GRID1) {
        const int p    = t >> 7;
        const int row0 = (t & 127) * 64;
        const float* Ap = A + (size_t)p * N_NODES * N_NODES;

        float acc[2][8][4];
#pragma unroll
        for (int mt = 0; mt < 2; mt++)
#pragma unroll
            for (int nt = 0; nt < 8; nt++)
#pragma unroll
                for (int i = 0; i < 4; i++) acc[mt][nt][i] = 0.f;

        float4 buf[4];                     // single A staging buffer (regs)

        auto ldgA = [&](int j) {           // load A slab for local iter j
            const int k0 = (2 * j + grp) * 64;
#pragma unroll
            for (int i = 0; i < 4; i++)
                buf[i] = *(const float4*)(Ap + (size_t)(row0 + lr0 + 16 * i) * N_NODES + k0 + lk);
        };
        auto stsA = [&](int j) {           // convert + store into stage j&1
            const uint32_t sa = aSts + (j & 1) * A_STAGEB;
#pragma unroll
            for (int i = 0; i < 4; i++) {
                uint32_t u0 = h2u(__floats2half2_rn(buf[i].x, buf[i].y));
                uint32_t u1 = h2u(__floats2half2_rn(buf[i].z, buf[i].w));
                sts64(sa + (uint32_t)(lr0 + 16 * i) * A_ROWB + (uint32_t)lk * 2, u0, u1);
            }
        };
        auto cpB = [&](int j) {            // async B tile into stage j&1
            const uint32_t sb = bCp + (j & 1) * B_STAGEB;
            const int k0 = (2 * j + grp) * 64;
#pragma unroll
            for (int i = 0; i < 8; i++) {
                int idx = gtid + i * 256;
                int n = idx >> 3, c = idx & 7;
                cp_async16(sb + (uint32_t)n * B_ROWB + c * 16,
                           g_Xh + (size_t)n * N_NODES + k0 + c * 8);
            }
            cp_commit();
        };

        // prologue: A(0) ldg+sts, A(1) ldg into regs, B(0) in flight
        ldgA(0); cpB(0); stsA(0); ldgA(1);

        for (int j = 0; j < NTG; j++) {
            bar_named(barId, 256);               // group done reading stage (j+1)&1
            if (j + 1 < NTG) { cpB(j + 1); cp_wait<1>(); }
            else             cp_wait<0>();
            bar_named(barId, 256);               // B(j)/A(j) visible to whole group

            const uint32_t aS = aFrag + (j & 1) * A_STAGEB;
            const uint32_t bS = bFrag + (j & 1) * B_STAGEB;
#pragma unroll
            for (int k16 = 0; k16 < 4; k16++) {
                const uint32_t off = k16 * 32;
                // A fragments for both m-tiles (8 lds32, batched at k16 top)
                uint32_t a0a = lds32(aS + off);
                uint32_t a1a = lds32(aS + off + 8 * A_ROWB);
                uint32_t a2a = lds32(aS + off + 16);
                uint32_t a3a = lds32(aS + off + 8 * A_ROWB + 16);
                uint32_t a0b = lds32(aS + off + 16 * A_ROWB);
                uint32_t a1b = lds32(aS + off + 24 * A_ROWB);
                uint32_t a2b = lds32(aS + off + 16 * A_ROWB + 16);
                uint32_t a3b = lds32(aS + off + 24 * A_ROWB + 16);
                // B fragments: 1-deep software pipeline over nt
                uint32_t b0c, b1c, b0n, b1n;
                lds64(b0c, b1c, bS + off);       // nt = 0
#pragma unroll
                for (int nt = 0; nt < 8; nt++) {
                    if (nt < 7) lds64(b0n, b1n, bS + (nt + 1) * 8 * B_ROWB + off);
                    mma_f16(acc[0][nt], a0a, a1a, a2a, a3a, b0c, b1c);
                    mma_f16(acc[1][nt], a0b, a1b, a2b, a3b, b0c, b1c);
                    b0c = b0n; b1c = b1n;
                }
            }

            // deferred producer work for the NEXT stages (post-compute):
            if (j + 1 < NTG) stsA(j + 1);        // buf holds slab j+1
            if (j + 2 < NTG) ldgA(j + 2);        // refill buf (lands during j+1)
        }

        // ---- cross-group accumulator reduction + store ----
        const uint32_t red = base + GRP_BYTES + 2 * A_STAGEB;  // group1's B region (80KB >= 64KB)
        __syncthreads();
        if (grp == 1) {
            const uint32_t w = red + (uint32_t)wid_g * 8192 + lane * 16;
#pragma unroll
            for (int mt = 0; mt < 2; mt++)
#pragma unroll
                for (int nt = 0; nt < 8; nt++)
                    sts128f(w + (mt * 8 + nt) * 512,
                            acc[mt][nt][0], acc[mt][nt][1], acc[mt][nt][2], acc[mt][nt][3]);
        }
        __syncthreads();
        if (grp == 0) {
            const uint32_t r = red + (uint32_t)wid_g * 8192 + lane * 16;
            float* Mo = g_M + (size_t)p * N_NODES * DIM;
#pragma unroll
            for (int mt = 0; mt < 2; mt++) {
                const int rr = row0 + rw0 + mt * 16 + g;
#pragma unroll
                for (int nt = 0; nt < 8; nt++) {
                    float x, y, z, w2;
                    lds128f(x, y, z, w2, r + (mt * 8 + nt) * 512);
                    const int c = cw0 + nt * 8 + 2 * tq;
                    *(float2*)&Mo[(size_t)rr * DIM + c] =
                        make_float2(acc[mt][nt][0] + x, acc[mt][nt][1] + y);
                    *(float2*)&Mo[(size_t)(rr + 8) * DIM + c] =
                        make_float2(acc[mt][nt][2] + z, acc[mt][nt][3] + w2);
                }
            }
        }
        __syncthreads();   // red region reused as B stages next tile
    }
}

// ---------------------------------------------------------------------------
// Kernel 2:  out = relu( [X | S1 | S2] @ [W0 | W1 | W2]^T + bias )   (tf32)
// ---------------------------------------------------------------------------
#define TS_STRIDE 36
__global__ void __launch_bounds__(256)
volterra_gemm2(const float* __restrict__ X, const float* __restrict__ W,
               const float* __restrict__ bvec, float* __restrict__ out) {
    __shared__ float Ts[64][TS_STRIDE];
    __shared__ float Ws[128][TS_STRIDE];

    const int row0 = blockIdx.x * 64;
    const int col0 = blockIdx.y * 128;
    const int tid  = threadIdx.x;
    const int wid  = tid >> 5;
    const int lane = tid & 31;
    const int warpRow = (wid >> 2) * 32;
    const int warpCol = (wid & 3) * 32;

    float acc[2][4][4];
#pragma unroll
    for (int mt = 0; mt < 2; mt++)
#pragma unroll
        for (int nt = 0; nt < 4; nt++)
#pragma unroll
            for (int i = 0; i < 4; i++) acc[mt][nt][i] = 0.f;

    const size_t MSZ = (size_t)N_NODES * DIM;

    for (int kc = 0; kc < 24; kc++) {
        const int r  = kc >> 3;
        const int k0 = (kc & 7) * 32;

#pragma unroll
        for (int i = 0; i < 2; i++) {
            int idx = tid + i * 256;
            int rr = idx >> 3, c4 = idx & 7;
            size_t gidx = (size_t)(row0 + rr) * DIM + k0 + c4 * 4;
            float4 v;
            if (r == 0) {
                v = *(const float4*)&X[gidx];
            } else {
                float4 m0 = *(const float4*)&g_M[gidx];
                float4 m1 = *(const float4*)&g_M[MSZ + gidx];
                float4 m2 = *(const float4*)&g_M[2 * MSZ + gidx];
                if (r == 1) {
                    v.x = m0.x + m1.x + m2.x;  v.y = m0.y + m1.y + m2.y;
                    v.z = m0.z + m1.z + m2.z;  v.w = m0.w + m1.w + m2.w;
                } else {
                    float s, q;
                    s = m0.x + m1.x + m2.x; q = m0.x*m0.x + m1.x*m1.x + m2.x*m2.x; v.x = 0.5f*(s*s + q);
                    s = m0.y + m1.y + m2.y; q = m0.y*m0.y + m1.y*m1.y + m2.y*m2.y; v.y = 0.5f*(s*s + q);
                    s = m0.z + m1.z + m2.z; q = m0.z*m0.z + m1.z*m1.z + m2.z*m2.z; v.z = 0.5f*(s*s + q);
                    s = m0.w + m1.w + m2.w; q = m0.w*m0.w + m1.w*m1.w + m2.w*m2.w; v.w = 0.5f*(s*s + q);
                }
            }
            *(float4*)&Ts[rr][c4 * 4] = v;
        }
        const float* Wr = W + (size_t)r * DIM * DIM;
#pragma unroll
        for (int i = 0; i < 4; i++) {
            int idx = tid + i * 256;
            int d = idx >> 3, c4 = idx & 7;
            *(float4*)&Ws[d][c4 * 4] = *(const float4*)&Wr[(size_t)(col0 + d) * DIM + k0 + c4 * 4];
        }
        __syncthreads();

#pragma unroll
        for (int k8 = 0; k8 < 4; k8++) {
            const int kb = k8 * 8;
            uint32_t af[2][4];
#pragma unroll
            for (int mt = 0; mt < 2; mt++) {
                int rr = warpRow + mt * 16 + (lane >> 2);
                int c = kb + (lane & 3);
                af[mt][0] = f2tf32(Ts[rr][c]);
                af[mt][1] = f2tf32(Ts[rr + 8][c]);
                af[mt][2] = f2tf32(Ts[rr][c + 4]);
                af[mt][3] = f2tf32(Ts[rr + 8][c + 4]);
            }
#pragma unroll
            for (int nt = 0; nt < 4; nt++) {
                int d = warpCol + nt * 8 + (lane >> 2);
                int k = kb + (lane & 3);
                uint32_t b0 = f2tf32(Ws[d][k]);
                uint32_t b1 = f2tf32(Ws[d][k + 4]);
                mma_tf32(acc[0][nt], af[0][0], af[0][1], af[0][2], af[0][3], b0, b1);
                mma_tf32(acc[1][nt], af[1][0], af[1][1], af[1][2], af[1][3], b0, b1);
            }
        }
        __syncthreads();
    }

#pragma unroll
    for (int nt = 0; nt < 4; nt++) {
        int c  = col0 + warpCol + nt * 8 + 2 * (lane & 3);
        float bias0 = bvec[c]     + 3.f * bvec[DIM + c]     + 6.f * bvec[2 * DIM + c];
        float bias1 = bvec[c + 1] + 3.f * bvec[DIM + c + 1] + 6.f * bvec[2 * DIM + c + 1];
#pragma unroll
        for (int mt = 0; mt < 2; mt++) {
            int rr = row0 + warpRow + mt * 16 + (lane >> 2);
            float2 v0 = make_float2(fmaxf(acc[mt][nt][0] + bias0, 0.f),
                                    fmaxf(acc[mt][nt][1] + bias1, 0.f));
            float2 v1 = make_float2(fmaxf(acc[mt][nt][2] + bias0, 0.f),
                                    fmaxf(acc[mt][nt][3] + bias1, 0.f));
            *(float2*)&out[(size_t)rr * DIM + c]       = v0;
            *(float2*)&out[(size_t)(rr + 8) * DIM + c] = v1;
        }
    }
}

// ---------------------------------------------------------------------------
extern "C" void kernel_launch(void* const* d_in, const int* in_sizes, int n_in,
                              void* d_out, int out_size) {
    const float *X = nullptr, *A = nullptr, *W = nullptr, *b = nullptr;
    for (int i = 0; i < n_in; i++) {
        long long s = in_sizes[i];
        if      (s == (long long)N_NODES * DIM)            X = (const float*)d_in[i];
        else if (s == (long long)NPOW * N_NODES * N_NODES) A = (const float*)d_in[i];
        else if (s == (long long)NPOW * DIM * DIM)         W = (const float*)d_in[i];
        else if (s == (long long)NPOW * DIM)               b = (const float*)d_in[i];
    }

    cudaFuncSetAttribute(volterra_gemm1,
                         cudaFuncAttributeMaxDynamicSharedMemorySize, G1_SMEM);

    prep_xh<<<dim3(N_NODES / 32, DIM / 32), dim3(32, 8)>>>(X);
    volterra_gemm1<<<GRID1, 512, G1_SMEM>>>(A);
    volterra_gemm2<<<dim3(N_NODES / 64, 2), 256>>>(X, W, b, (float*)d_out);
}

// round 16
// speedup vs baseline: 1.6478x; 1.1494x over previous
#include <cuda_runtime.h>
#include <cuda_fp16.h>
#include <cstdint>

// ---------------------------------------------------------------------------
// VolterraGraphConvLayer on GB300 (sm_103 non-'a': legacy mma.sync only).
//   gemm1: M[p] = A[p] @ X  via fp16 mma.m16n8k16.  R11-proven 8-warp GEMM
//          body, but as a 256-thread CTA with 99KB smem so TWO CTAs co-reside
//          per SM in independent barrier domains (anti-phase overlap of
//          crossbar and tensor phases). Grid 384, tile = blockIdx (HW
//          work-stealing balances the tail).
//   gemm2: out = relu([X|S1|S2] @ [W0|W1|W2]^T + bias)  via tf32 mma.
// ---------------------------------------------------------------------------

#define N_NODES 8192
#define DIM     256
#define NPOW    3

__device__ __align__(1024) float  g_M [(size_t)NPOW * N_NODES * DIM];  // 24 MB
__device__ __align__(1024) __half g_Xh[(size_t)DIM * N_NODES];          // 4 MB [feat][node-perm]

// ---------------- PTX helpers ----------------
__device__ __forceinline__ uint32_t smem_u32(const void* p) {
    return (uint32_t)__cvta_generic_to_shared(p);
}
__device__ __forceinline__ void cp_async16(uint32_t dst, const void* src) {
    asm volatile("cp.async.cg.shared.global [%0], [%1], 16;\n" :: "r"(dst), "l"(src));
}
__device__ __forceinline__ void cp_commit() { asm volatile("cp.async.commit_group;\n"); }
template <int N> __device__ __forceinline__ void cp_wait() {
    asm volatile("cp.async.wait_group %0;\n" :: "n"(N));
}
__device__ __forceinline__ uint32_t f2tf32(float x) {
    uint32_t r; asm("cvt.rna.tf32.f32 %0, %1;\n" : "=r"(r) : "f"(x)); return r;
}
__device__ __forceinline__ uint32_t lds32(uint32_t a) {
    uint32_t r; asm volatile("ld.shared.b32 %0, [%1];" : "=r"(r) : "r"(a)); return r;
}
__device__ __forceinline__ void lds64(uint32_t& x, uint32_t& y, uint32_t a) {
    asm volatile("ld.shared.v2.b32 {%0,%1}, [%2];" : "=r"(x), "=r"(y) : "r"(a));
}
__device__ __forceinline__ void sts64(uint32_t a, uint32_t x, uint32_t y) {
    asm volatile("st.shared.v2.b32 [%0], {%1,%2};" :: "r"(a), "r"(x), "r"(y));
}
__device__ __forceinline__ void mma_f16(float c[4],
                                        uint32_t a0, uint32_t a1, uint32_t a2, uint32_t a3,
                                        uint32_t b0, uint32_t b1) {
    asm volatile(
        "mma.sync.aligned.m16n8k16.row.col.f32.f16.f16.f32 "
        "{%0,%1,%2,%3}, {%4,%5,%6,%7}, {%8,%9}, {%0,%1,%2,%3};\n"
        : "+f"(c[0]), "+f"(c[1]), "+f"(c[2]), "+f"(c[3])
        : "r"(a0), "r"(a1), "r"(a2), "r"(a3), "r"(b0), "r"(b1));
}
__device__ __forceinline__ void mma_tf32(float c[4],
                                         uint32_t a0, uint32_t a1, uint32_t a2, uint32_t a3,
                                         uint32_t b0, uint32_t b1) {
    asm volatile(
        "mma.sync.aligned.m16n8k8.row.col.f32.tf32.tf32.f32 "
        "{%0,%1,%2,%3}, {%4,%5,%6,%7}, {%8,%9}, {%0,%1,%2,%3};\n"
        : "+f"(c[0]), "+f"(c[1]), "+f"(c[2]), "+f"(c[3])
        : "r"(a0), "r"(a1), "r"(a2), "r"(a3), "r"(b0), "r"(b1));
}
__device__ __forceinline__ uint32_t h2u(__half2 h) {
    return *reinterpret_cast<uint32_t*>(&h);
}

// k-within-16 interleave: positions 4t..4t+3 hold original k {2t,2t+1,2t+8,2t+9}
__device__ __forceinline__ int hperm(int k) {
    return ((k & 7) >> 1) * 4 + ((k >> 3) & 1) * 2 + (k & 1);
}

// ---------------------------------------------------------------------------
// Kernel 0: g_Xh[feat][perm(node)] = fp16_rna(X[node][feat])
// ---------------------------------------------------------------------------
__global__ void __launch_bounds__(256)
prep_xh(const float* __restrict__ X) {
    __shared__ float t[32][33];
    const int n0 = blockIdx.x * 32;
    const int f0 = blockIdx.y * 32;
    const int tx = threadIdx.x, ty = threadIdx.y;
#pragma unroll
    for (int j = 0; j < 32; j += 8)
        t[ty + j][tx] = X[(size_t)(n0 + ty + j) * DIM + f0 + tx];
    __syncthreads();
    const int node = n0 + tx;
    const int ndst = (node & ~15) + hperm(node & 15);
#pragma unroll
    for (int j = 0; j < 32; j += 8)
        g_Xh[(size_t)(f0 + ty + j) * N_NODES + ndst] = __float2half_rn(t[tx][ty + j]);
}

// ---------------------------------------------------------------------------
// Kernel 1: fp16 GEMM, 256 threads/CTA, 2 CTAs per SM (independent pipelines).
// Tile 64x256, BK=64, NT=128 serial kts per CTA.
// smem/CTA: A 2 stages x 64x144B + B 2 stages x 256x160B = 100352 B.
// ---------------------------------------------------------------------------
#define A_ROWB    144
#define B_ROWB    160
#define A_STAGEB  (64 * A_ROWB)                   // 9216
#define B_STAGEB  (256 * B_ROWB)                  // 40960
#define G1_SMEM   (2 * A_STAGEB + 2 * B_STAGEB + 1024)   // 101376
#define NT        128
#define TILES     (NPOW * (N_NODES / 64))         // 384

__global__ void __launch_bounds__(256, 2)
volterra_gemm1(const float* __restrict__ A) {
    extern __shared__ char dsm[];
    const uint32_t base = (smem_u32(dsm) + 1023) & ~1023u;

    const int tid  = threadIdx.x;
    const int wid  = tid >> 5;            // 0..7
    const int lane = tid & 31;
    const int g    = lane >> 2;
    const int tq   = lane & 3;
    const int rw0  = (wid >> 2) * 32;     // 2 row groups of 32
    const int cw0  = (wid & 3) * 64;      // 4 col groups of 64

    const int lr0 = tid >> 4;             // A-load rows: lr0 + 16*i
    const int lk  = (tid & 15) * 4;

    const uint32_t aSts  = base;
    const uint32_t bCp   = base + 2 * A_STAGEB;
    const uint32_t aFrag = base + (uint32_t)(rw0 + g) * A_ROWB + tq * 4;
    const uint32_t bFrag = bCp + (uint32_t)(cw0 + g) * B_ROWB + tq * 8;

    const int t    = blockIdx.x;          // one tile per CTA; HW balances
    const int p    = t >> 7;
    const int row0 = (t & 127) * 64;
    const float* Ap = A + (size_t)p * N_NODES * N_NODES;

    float acc[2][8][4];
#pragma unroll
    for (int mt = 0; mt < 2; mt++)
#pragma unroll
        for (int nt = 0; nt < 8; nt++)
#pragma unroll
            for (int i = 0; i < 4; i++) acc[mt][nt][i] = 0.f;

    float4 buf[4];                        // A staging (regs)

    auto ldgA = [&](int kt) {
        const int k0 = kt * 64;
#pragma unroll
        for (int i = 0; i < 4; i++)
            buf[i] = *(const float4*)(Ap + (size_t)(row0 + lr0 + 16 * i) * N_NODES + k0 + lk);
    };
    auto stsA = [&](int kt) {             // convert + store into stage kt&1
        const uint32_t sa = aSts + (kt & 1) * A_STAGEB;
#pragma unroll
        for (int i = 0; i < 4; i++) {
            uint32_t u0 = h2u(__floats2half2_rn(buf[i].x, buf[i].y));
            uint32_t u1 = h2u(__floats2half2_rn(buf[i].z, buf[i].w));
            sts64(sa + (uint32_t)(lr0 + 16 * i) * A_ROWB + (uint32_t)lk * 2, u0, u1);
        }
    };
    auto cpB = [&](int kt) {              // async B tile into stage kt&1
        const uint32_t sb = bCp + (kt & 1) * B_STAGEB;
        const int k0 = kt * 64;
#pragma unroll
        for (int i = 0; i < 8; i++) {
            int idx = tid + i * 256;
            int n = idx >> 3, c = idx & 7;
            cp_async16(sb + (uint32_t)n * B_ROWB + c * 16,
                       g_Xh + (size_t)n * N_NODES + k0 + c * 8);
        }
        cp_commit();
    };

    // prologue: A(0) ldg+sts, A(1) ldg into regs, B(0) in flight
    ldgA(0); cpB(0); stsA(0); ldgA(1);

    for (int j = 0; j < NT; j++) {
        __syncthreads();                       // readers of stage (j+1)&1 done
        if (j + 1 < NT) { cpB(j + 1); cp_wait<1>(); }
        else            cp_wait<0>();
        __syncthreads();                       // B(j)/A(j) visible to whole CTA

        const uint32_t aS = aFrag + (j & 1) * A_STAGEB;
        const uint32_t bS = bFrag + (j & 1) * B_STAGEB;
#pragma unroll
        for (int k16 = 0; k16 < 4; k16++) {
            const uint32_t off = k16 * 32;
            // A fragments for both m-tiles (8 lds32, batched at k16 top)
            uint32_t a0a = lds32(aS + off);
            uint32_t a1a = lds32(aS + off + 8 * A_ROWB);
            uint32_t a2a = lds32(aS + off + 16);
            uint32_t a3a = lds32(aS + off + 8 * A_ROWB + 16);
            uint32_t a0b = lds32(aS + off + 16 * A_ROWB);
            uint32_t a1b = lds32(aS + off + 24 * A_ROWB);
            uint32_t a2b = lds32(aS + off + 16 * A_ROWB + 16);
            uint32_t a3b = lds32(aS + off + 24 * A_ROWB + 16);
            // B fragments: 8 lds64, batched
            uint32_t bb[16];
#pragma unroll
            for (int nt = 0; nt < 8; nt++)
                lds64(bb[2 * nt], bb[2 * nt + 1], bS + nt * 8 * B_ROWB + off);
            // 16 mma
#pragma unroll
            for (int nt = 0; nt < 8; nt++) {
                mma_f16(acc[0][nt], a0a, a1a, a2a, a3a, bb[2 * nt], bb[2 * nt + 1]);
                mma_f16(acc[1][nt], a0b, a1b, a2b, a3b, bb[2 * nt], bb[2 * nt + 1]);
            }
        }

        // deferred producer work for the NEXT stages (post-compute):
        if (j + 1 < NT) stsA(j + 1);           // buf holds slab j+1
        if (j + 2 < NT) ldgA(j + 2);           // refill buf (lands during j+1)
    }

    // ---- epilogue: direct store of 64x256 f32 tile ----
    float* Mo = g_M + (size_t)p * N_NODES * DIM;
#pragma unroll
    for (int mt = 0; mt < 2; mt++) {
        const int r = row0 + rw0 + mt * 16 + g;
#pragma unroll
        for (int nt = 0; nt < 8; nt++) {
            const int c = cw0 + nt * 8 + 2 * tq;
            *(float2*)&Mo[(size_t)r * DIM + c] =
                make_float2(acc[mt][nt][0], acc[mt][nt][1]);
            *(float2*)&Mo[(size_t)(r + 8) * DIM + c] =
                make_float2(acc[mt][nt][2], acc[mt][nt][3]);
        }
    }
}

// ---------------------------------------------------------------------------
// Kernel 2:  out = relu( [X | S1 | S2] @ [W0 | W1 | W2]^T + bias )   (tf32)
// ---------------------------------------------------------------------------
#define TS_STRIDE 36
__global__ void __launch_bounds__(256)
volterra_gemm2(const float* __restrict__ X, const float* __restrict__ W,
               const float* __restrict__ bvec, float* __restrict__ out) {
    __shared__ float Ts[64][TS_STRIDE];
    __shared__ float Ws[128][TS_STRIDE];

    const int row0 = blockIdx.x * 64;
    const int col0 = blockIdx.y * 128;
    const int tid  = threadIdx.x;
    const int wid  = tid >> 5;
    const int lane = tid & 31;
    const int warpRow = (wid >> 2) * 32;
    const int warpCol = (wid & 3) * 32;

    float acc[2][4][4];
#pragma unroll
    for (int mt = 0; mt < 2; mt++)
#pragma unroll
        for (int nt = 0; nt < 4; nt++)
#pragma unroll
            for (int i = 0; i < 4; i++) acc[mt][nt][i] = 0.f;

    const size_t MSZ = (size_t)N_NODES * DIM;

    for (int kc = 0; kc < 24; kc++) {
        const int r  = kc >> 3;
        const int k0 = (kc & 7) * 32;

#pragma unroll
        for (int i = 0; i < 2; i++) {
            int idx = tid + i * 256;
            int rr = idx >> 3, c4 = idx & 7;
            size_t gidx = (size_t)(row0 + rr) * DIM + k0 + c4 * 4;
            float4 v;
            if (r == 0) {
                v = *(const float4*)&X[gidx];
            } else {
                float4 m0 = *(const float4*)&g_M[gidx];
                float4 m1 = *(const float4*)&g_M[MSZ + gidx];
                float4 m2 = *(const float4*)&g_M[2 * MSZ + gidx];
                if (r == 1) {
                    v.x = m0.x + m1.x + m2.x;  v.y = m0.y + m1.y + m2.y;
                    v.z = m0.z + m1.z + m2.z;  v.w = m0.w + m1.w + m2.w;
                } else {
                    float s, q;
                    s = m0.x + m1.x + m2.x; q = m0.x*m0.x + m1.x*m1.x + m2.x*m2.x; v.x = 0.5f*(s*s + q);
                    s = m0.y + m1.y + m2.y; q = m0.y*m0.y + m1.y*m1.y + m2.y*m2.y; v.y = 0.5f*(s*s + q);
                    s = m0.z + m1.z + m2.z; q = m0.z*m0.z + m1.z*m1.z + m2.z*m2.z; v.z = 0.5f*(s*s + q);
                    s = m0.w + m1.w + m2.w; q = m0.w*m0.w + m1.w*m1.w + m2.w*m2.w; v.w = 0.5f*(s*s + q);
                }
            }
            *(float4*)&Ts[rr][c4 * 4] = v;
        }
        const float* Wr = W + (size_t)r * DIM * DIM;
#pragma unroll
        for (int i = 0; i < 4; i++) {
            int idx = tid + i * 256;
            int d = idx >> 3, c4 = idx & 7;
            *(float4*)&Ws[d][c4 * 4] = *(const float4*)&Wr[(size_t)(col0 + d) * DIM + k0 + c4 * 4];
        }
        __syncthreads();

#pragma unroll
        for (int k8 = 0; k8 < 4; k8++) {
            const int kb = k8 * 8;
            uint32_t af[2][4];
#pragma unroll
            for (int mt = 0; mt < 2; mt++) {
                int rr = warpRow + mt * 16 + (lane >> 2);
                int c = kb + (lane & 3);
                af[mt][0] = f2tf32(Ts[rr][c]);
                af[mt][1] = f2tf32(Ts[rr + 8][c]);
                af[mt][2] = f2tf32(Ts[rr][c + 4]);
                af[mt][3] = f2tf32(Ts[rr + 8][c + 4]);
            }
#pragma unroll
            for (int nt = 0; nt < 4; nt++) {
                int d = warpCol + nt * 8 + (lane >> 2);
                int k = kb + (lane & 3);
                uint32_t b0 = f2tf32(Ws[d][k]);
                uint32_t b1 = f2tf32(Ws[d][k + 4]);
                mma_tf32(acc[0][nt], af[0][0], af[0][1], af[0][2], af[0][3], b0, b1);
                mma_tf32(acc[1][nt], af[1][0], af[1][1], af[1][2], af[1][3], b0, b1);
            }
        }
        __syncthreads();
    }

#pragma unroll
    for (int nt = 0; nt < 4; nt++) {
        int c  = col0 + warpCol + nt * 8 + 2 * (lane & 3);
        float bias0 = bvec[c]     + 3.f * bvec[DIM + c]     + 6.f * bvec[2 * DIM + c];
        float bias1 = bvec[c + 1] + 3.f * bvec[DIM + c + 1] + 6.f * bvec[2 * DIM + c + 1];
#pragma unroll
        for (int mt = 0; mt < 2; mt++) {
            int rr = row0 + warpRow + mt * 16 + (lane >> 2);
            float2 v0 = make_float2(fmaxf(acc[mt][nt][0] + bias0, 0.f),
                                    fmaxf(acc[mt][nt][1] + bias1, 0.f));
            float2 v1 = make_float2(fmaxf(acc[mt][nt][2] + bias0, 0.f),
                                    fmaxf(acc[mt][nt][3] + bias1, 0.f));
            *(float2*)&out[(size_t)rr * DIM + c]       = v0;
            *(float2*)&out[(size_t)(rr + 8) * DIM + c] = v1;
        }
    }
}

// ---------------------------------------------------------------------------
extern "C" void kernel_launch(void* const* d_in, const int* in_sizes, int n_in,
                              void* d_out, int out_size) {
    const float *X = nullptr, *A = nullptr, *W = nullptr, *b = nullptr;
    for (int i = 0; i < n_in; i++) {
        long long s = in_sizes[i];
        if      (s == (long long)N_NODES * DIM)            X = (const float*)d_in[i];
        else if (s == (long long)NPOW * N_NODES * N_NODES) A = (const float*)d_in[i];
        else if (s == (long long)NPOW * DIM * DIM)         W = (const float*)d_in[i];
        else if (s == (long long)NPOW * DIM)               b = (const float*)d_in[i];
    }

    cudaFuncSetAttribute(volterra_gemm1,
                         cudaFuncAttributeMaxDynamicSharedMemorySize, G1_SMEM);

    prep_xh<<<dim3(N_NODES / 32, DIM / 32), dim3(32, 8)>>>(X);
    volterra_gemm1<<<TILES, 256, G1_SMEM>>>(A);
    volterra_gemm2<<<dim3(N_NODES / 64, 2), 256>>>(X, W, b, (float*)d_out);
}